// round 2
// baseline (speedup 1.0000x reference)
#include <cuda_runtime.h>

// ---------------- problem constants ----------------
#define BATCH 256
#define TT    200
#define EMBD  300
#define PD    30
#define MEM   300
#define INX   360      // EMB + POSD + NERD
#define KDEP  5

constexpr long BT = (long)BATCH * TT;   // 51200

// ---------------- scratch (device globals, no allocation) ----------------
__device__ float g_x[BT * INX];   // [BT,360] concat(word,pos,ner)
__device__ float g_y[BT * MEM];   // x @ W0a
__device__ float g_c[BT * MEM];   // (chosen + dep_emb[1]) @ W0d + 2*b0
__device__ float g_h[BT * MEM];   // layer-0 output
__device__ float g_z[BT * MEM];   // h @ W1
__device__ float g_rd[BT];        // 1/denom

// ---------------- K0: row/col sums of A -> 1/denom, out_mask ----------------
// one block per batch; column sums are coalesced (threads across columns),
// row sums via warp-reduce + shared atomics.
__global__ void k_prep(const int* __restrict__ adj, float* __restrict__ out,
                       int write_mask) {
    int b = blockIdx.x;
    const int* Ab = adj + (long)b * TT * TT;
    int t = threadIdx.x;

    __shared__ int rows[TT];
    for (int i = t; i < TT; i += blockDim.x) rows[i] = 0;
    __syncthreads();

    int cs = 0;
    for (int s = 0; s < TT; s++) {
        int v = (t < TT) ? Ab[s * TT + t] : 0;
        cs += v;
        #pragma unroll
        for (int o = 16; o > 0; o >>= 1) v += __shfl_down_sync(0xffffffff, v, o);
        if ((threadIdx.x & 31) == 0) atomicAdd(&rows[s], v);
    }
    __syncthreads();

    if (t < TT) {
        int rs = rows[t];
        g_rd[b * TT + t] = 1.0f / (float)(rs + 1);
        if (write_mask)
            out[BT * MEM + (long)b * TT + t] = (rs + cs == 0) ? 1.0f : 0.0f;
    }
}

// ---------------- K1: embedding gather + dep vector c ----------------
// one block per token (bt). 384 threads: 0..359 gather x, then 0..29 build
// chosen+loop, then 0..299 compute c = g @ W0d + 2*b0.
__global__ void k_embed(const int* __restrict__ words, const int* __restrict__ pos,
                        const int* __restrict__ ner, const int* __restrict__ dep_ids,
                        const int* __restrict__ dep_mask,
                        const float* __restrict__ wemb, const float* __restrict__ pemb,
                        const float* __restrict__ nemb, const float* __restrict__ demb,
                        const float* __restrict__ W0w, const float* __restrict__ W0b) {
    long bt = blockIdx.x;
    int tid = threadIdx.x;
    __shared__ float sg[PD];

    if (tid < EMBD) {
        int w = words[bt];
        g_x[bt * INX + tid] = wemb[(long)w * EMBD + tid];
    } else if (tid < EMBD + PD) {
        int p = pos[bt];
        g_x[bt * INX + tid] = pemb[p * PD + (tid - EMBD)];
    } else if (tid < INX) {
        int nr = ner[bt];
        g_x[bt * INX + tid] = nemb[nr * PD + (tid - EMBD - PD)];
    }

    if (tid < PD) {
        float s = 0.0f;
        int any = 0;
        #pragma unroll
        for (int j = 0; j < KDEP; j++) {
            int m  = dep_mask[bt * KDEP + j];
            int id = dep_ids[bt * KDEP + j];
            any += m;
            s += m ? demb[id * PD + tid] : 0.0f;
        }
        if (any == 0) s = demb[tid];            // dep_emb[0]
        sg[tid] = s + demb[PD + tid];           // + dep_emb[SELF_LOOP=1]
    }
    __syncthreads();

    if (tid < MEM) {
        const float* Wd = W0w + (long)INX * MEM;   // rows 360..389 of W0
        float acc = 2.0f * W0b[tid];
        #pragma unroll
        for (int k = 0; k < PD; k++) acc += sg[k] * Wd[k * MEM + tid];
        g_c[bt * MEM + tid] = acc;
    }
}

// ---------------- K2/K4: generic fp32 GEMM  C[M,N] = A[M,K] @ B[K,N] ----------------
// 128x64 block tile, BK=16, 256 threads, each computes 8x4.
template <int BM, int BN, int BK, int TM, int TN>
__global__ void k_gemm(const float* __restrict__ A, const float* __restrict__ B,
                       float* __restrict__ C, int M, int N, int K) {
    __shared__ float As[BK][BM + 4];
    __shared__ float Bs[BK][BN];
    const int NTH = (BM / TM) * (BN / TN);

    int tid = threadIdx.x;
    int tx = tid % (BN / TN);
    int ty = tid / (BN / TN);
    int m0 = blockIdx.y * BM, n0 = blockIdx.x * BN;

    float acc[TM][TN];
    #pragma unroll
    for (int i = 0; i < TM; i++)
        #pragma unroll
        for (int j = 0; j < TN; j++) acc[i][j] = 0.0f;

    for (int k0 = 0; k0 < K; k0 += BK) {
        #pragma unroll 4
        for (int idx = tid; idx < BM * BK; idx += NTH) {
            int r = idx / BK, c = idx % BK;
            float v = 0.0f;
            if (m0 + r < M && k0 + c < K) v = A[(long)(m0 + r) * K + k0 + c];
            As[c][r] = v;
        }
        #pragma unroll 4
        for (int idx = tid; idx < BK * BN; idx += NTH) {
            int r = idx / BN, c = idx % BN;
            float v = 0.0f;
            if (k0 + r < K && n0 + c < N) v = B[(long)(k0 + r) * N + n0 + c];
            Bs[r][c] = v;
        }
        __syncthreads();

        #pragma unroll
        for (int k = 0; k < BK; k++) {
            float ra[TM], rb[TN];
            #pragma unroll
            for (int i = 0; i < TM; i++) ra[i] = As[k][ty * TM + i];
            #pragma unroll
            for (int j = 0; j < TN; j++) rb[j] = Bs[k][tx * TN + j];
            #pragma unroll
            for (int i = 0; i < TM; i++)
                #pragma unroll
                for (int j = 0; j < TN; j++) acc[i][j] += ra[i] * rb[j];
        }
        __syncthreads();
    }

    #pragma unroll
    for (int i = 0; i < TM; i++) {
        int m = m0 + ty * TM + i;
        if (m >= M) continue;
        #pragma unroll
        for (int j = 0; j < TN; j++) {
            int n = n0 + tx * TN + j;
            if (n < N) C[(long)m * N + n] = acc[i][j];
        }
    }
}

// ---------------- K3/K5: batched adjacency GEMM + fused epilogue ----------------
// out[b,t,:] = relu((A_b @ Y_b + Y_b[t,:] + add) * (1/denom[b,t]))
// add = addv[b,t,:] (layer 0) or 2*bias[:] (layer 1)
__global__ void k_adjgemm(const int* __restrict__ adj, const float* __restrict__ Y,
                          const float* __restrict__ addv, const float* __restrict__ bias,
                          float* __restrict__ out) {
    const int BM = 64, BN = 64, BK = 16, TM = 4, TN = 4;
    __shared__ float As[BK][BM + 4];
    __shared__ float Bs[BK][BN];

    int b = blockIdx.z;
    const int*   Ab = adj + (long)b * TT * TT;
    const float* Yb = Y + (long)b * TT * MEM;

    int tid = threadIdx.x;                 // 256
    int tx = tid % (BN / TN);              // 16
    int ty = tid / (BN / TN);              // 16
    int m0 = blockIdx.y * BM, n0 = blockIdx.x * BN;

    float acc[TM][TN];
    #pragma unroll
    for (int i = 0; i < TM; i++)
        #pragma unroll
        for (int j = 0; j < TN; j++) acc[i][j] = 0.0f;

    for (int k0 = 0; k0 < TT; k0 += BK) {
        #pragma unroll 4
        for (int idx = tid; idx < BM * BK; idx += 256) {
            int r = idx / BK, c = idx % BK;
            float v = 0.0f;
            if (m0 + r < TT && k0 + c < TT) v = (float)Ab[(m0 + r) * TT + k0 + c];
            As[c][r] = v;
        }
        #pragma unroll 4
        for (int idx = tid; idx < BK * BN; idx += 256) {
            int r = idx / BN, c = idx % BN;
            float v = 0.0f;
            if (k0 + r < TT && n0 + c < MEM) v = Yb[(k0 + r) * MEM + n0 + c];
            Bs[r][c] = v;
        }
        __syncthreads();

        #pragma unroll
        for (int k = 0; k < BK; k++) {
            float ra[TM], rb[TN];
            #pragma unroll
            for (int i = 0; i < TM; i++) ra[i] = As[k][ty * TM + i];
            #pragma unroll
            for (int j = 0; j < TN; j++) rb[j] = Bs[k][tx * TN + j];
            #pragma unroll
            for (int i = 0; i < TM; i++)
                #pragma unroll
                for (int j = 0; j < TN; j++) acc[i][j] += ra[i] * rb[j];
        }
        __syncthreads();
    }

    #pragma unroll
    for (int i = 0; i < TM; i++) {
        int t = m0 + ty * TM + i;
        if (t >= TT) continue;
        float rd = g_rd[b * TT + t];
        #pragma unroll
        for (int j = 0; j < TN; j++) {
            int n = n0 + tx * TN + j;
            if (n >= MEM) continue;
            long idx = ((long)b * TT + t) * MEM + n;
            float add = addv ? addv[idx] : 2.0f * bias[n];
            float v = (acc[i][j] + Yb[t * MEM + n] + add) * rd;
            out[idx] = v > 0.0f ? v : 0.0f;
        }
    }
}

// ---------------- launch ----------------
extern "C" void kernel_launch(void* const* d_in, const int* in_sizes, int n_in,
                              void* d_out, int out_size) {
    const int*   adj      = (const int*)d_in[0];
    const int*   words    = (const int*)d_in[1];
    const int*   pos      = (const int*)d_in[2];
    const int*   ner      = (const int*)d_in[3];
    const int*   dep_ids  = (const int*)d_in[4];
    const int*   dep_mask = (const int*)d_in[5];
    // d_in[6] = maxlen (compile-time TT)
    const float* wemb = (const float*)d_in[7];
    const float* pemb = (const float*)d_in[8];
    const float* nemb = (const float*)d_in[9];
    const float* demb = (const float*)d_in[10];
    const float* W0w  = (const float*)d_in[11];
    const float* W0b  = (const float*)d_in[12];
    const float* W1w  = (const float*)d_in[13];
    const float* W1b  = (const float*)d_in[14];
    float* out = (float*)d_out;

    float *px, *py, *pc, *ph, *pz;
    cudaGetSymbolAddress((void**)&px, g_x);
    cudaGetSymbolAddress((void**)&py, g_y);
    cudaGetSymbolAddress((void**)&pc, g_c);
    cudaGetSymbolAddress((void**)&ph, g_h);
    cudaGetSymbolAddress((void**)&pz, g_z);

    int write_mask = (out_size >= (int)(BT * MEM + BT));

    // K0: denoms + output mask
    k_prep<<<BATCH, 256>>>(adj, out, write_mask);

    // K1: gather x, build c
    k_embed<<<(int)BT, 384>>>(words, pos, ner, dep_ids, dep_mask,
                              wemb, pemb, nemb, demb, W0w, W0b);

    // K2: y = x @ W0a  (M=51200, K=360, N=300)
    {
        dim3 grid((MEM + 63) / 64, (int)((BT + 127) / 128));
        k_gemm<128, 64, 16, 8, 4><<<grid, 256>>>(px, W0w, py, (int)BT, MEM, INX);
    }

    // K3: h = relu((A@y + y + c)/denom)
    {
        dim3 grid((MEM + 63) / 64, (TT + 63) / 64, BATCH);
        k_adjgemm<<<grid, 256>>>(adj, py, pc, nullptr, ph);
    }

    // K4: z = h @ W1  (M=51200, K=300, N=300)
    {
        dim3 grid((MEM + 63) / 64, (int)((BT + 127) / 128));
        k_gemm<128, 64, 16, 8, 4><<<grid, 256>>>(ph, W1w, pz, (int)BT, MEM, MEM);
    }

    // K5: out = relu((A@z + z + 2*b1)/denom)
    {
        dim3 grid((MEM + 63) / 64, (TT + 63) / 64, BATCH);
        k_adjgemm<<<grid, 256>>>(adj, pz, nullptr, W1b, out);
    }
}

// round 3
// speedup vs baseline: 1.1743x; 1.1743x over previous
#include <cuda_runtime.h>

// ---------------- problem constants ----------------
#define BATCH 256
#define TT    200
#define EMBD  300
#define PD    30
#define MEM   300
#define INX   360      // EMB + POSD + NERD
#define KDEP  5

constexpr long BT = (long)BATCH * TT;   // 51200

// ---------------- scratch (device globals, no allocation) ----------------
__device__ float g_x[BT * INX];   // [BT,360] concat(word,pos,ner)
__device__ float g_y[BT * MEM];   // x @ W0a
__device__ float g_c[BT * MEM];   // (chosen + dep_emb[1]) @ W0d + 2*b0
__device__ float g_h[BT * MEM];   // layer-0 output
__device__ float g_z[BT * MEM];   // h @ W1
__device__ float g_rd[BT];        // 1/denom

// ---------------- K0: row/col sums of A -> 1/denom, out_mask ----------------
__global__ void k_prep(const int* __restrict__ adj, float* __restrict__ out,
                       int write_mask) {
    int b = blockIdx.x;
    const int* Ab = adj + (long)b * TT * TT;
    int t = threadIdx.x;

    __shared__ int rows[TT];
    for (int i = t; i < TT; i += blockDim.x) rows[i] = 0;
    __syncthreads();

    int cs = 0;
    for (int s = 0; s < TT; s++) {
        int v = (t < TT) ? Ab[s * TT + t] : 0;
        cs += v;
        #pragma unroll
        for (int o = 16; o > 0; o >>= 1) v += __shfl_down_sync(0xffffffff, v, o);
        if ((threadIdx.x & 31) == 0) atomicAdd(&rows[s], v);
    }
    __syncthreads();

    if (t < TT) {
        int rs = rows[t];
        g_rd[b * TT + t] = 1.0f / (float)(rs + 1);
        if (write_mask)
            out[BT * MEM + (long)b * TT + t] = (rs + cs == 0) ? 1.0f : 0.0f;
    }
}

// ---------------- K1: embedding gather + dep vector c ----------------
__global__ void k_embed(const int* __restrict__ words, const int* __restrict__ pos,
                        const int* __restrict__ ner, const int* __restrict__ dep_ids,
                        const int* __restrict__ dep_mask,
                        const float* __restrict__ wemb, const float* __restrict__ pemb,
                        const float* __restrict__ nemb, const float* __restrict__ demb,
                        const float* __restrict__ W0w, const float* __restrict__ W0b) {
    long bt = blockIdx.x;
    int tid = threadIdx.x;
    __shared__ float sg[PD];

    if (tid < EMBD) {
        int w = words[bt];
        g_x[bt * INX + tid] = wemb[(long)w * EMBD + tid];
    } else if (tid < EMBD + PD) {
        int p = pos[bt];
        g_x[bt * INX + tid] = pemb[p * PD + (tid - EMBD)];
    } else if (tid < INX) {
        int nr = ner[bt];
        g_x[bt * INX + tid] = nemb[nr * PD + (tid - EMBD - PD)];
    }

    if (tid < PD) {
        float s = 0.0f;
        int any = 0;
        #pragma unroll
        for (int j = 0; j < KDEP; j++) {
            int m  = dep_mask[bt * KDEP + j];
            int id = dep_ids[bt * KDEP + j];
            any += m;
            s += m ? demb[id * PD + tid] : 0.0f;
        }
        if (any == 0) s = demb[tid];            // dep_emb[0]
        sg[tid] = s + demb[PD + tid];           // + dep_emb[SELF_LOOP=1]
    }
    __syncthreads();

    if (tid < MEM) {
        const float* Wd = W0w + (long)INX * MEM;   // rows 360..389 of W0
        float acc = 2.0f * W0b[tid];
        #pragma unroll
        for (int k = 0; k < PD; k++) acc += sg[k] * Wd[k * MEM + tid];
        g_c[bt * MEM + tid] = acc;
    }
}

// ---------------- K2/K4: dense fp32 GEMM  C[M,N] = A[M,K] @ B[K,N] ----------------
// BM=128, BN=64, BK=20, 128 threads, 8x8 per-thread tile, fully float4.
// Requires: M % 128 == 0, K % 20 == 0, K % 4 == 0, N % 4 == 0 (holds here).
__global__ __launch_bounds__(128)
void k_gemm_v2(const float* __restrict__ A, const float* __restrict__ B,
               float* __restrict__ C, int M, int N, int K) {
    const int BM = 128, BN = 64, BK = 20;
    __shared__ float As[BK][BM + 4];
    __shared__ float Bs[BK][BN];

    int tid = threadIdx.x;
    int tx = tid & 7;        // 0..7  (8 col groups)
    int ty = tid >> 3;       // 0..15 (16 row groups)
    long m0 = (long)blockIdx.y * BM;
    int  n0 = blockIdx.x * BN;

    float acc[8][8];
    #pragma unroll
    for (int i = 0; i < 8; i++)
        #pragma unroll
        for (int j = 0; j < 8; j++) acc[i][j] = 0.0f;

    for (int k0 = 0; k0 < K; k0 += BK) {
        // A tile: 128x20, 640 float4, 5 per thread; transpose into As[k][m]
        #pragma unroll
        for (int i = 0; i < 5; i++) {
            int idx = tid + i * 128;
            int r = idx / (BK / 4);      // 0..127
            int c4 = idx % (BK / 4);     // 0..4
            float4 v = *(const float4*)&A[(m0 + r) * K + k0 + c4 * 4];
            As[c4 * 4 + 0][r] = v.x;
            As[c4 * 4 + 1][r] = v.y;
            As[c4 * 4 + 2][r] = v.z;
            As[c4 * 4 + 3][r] = v.w;
        }
        // B tile: 20x64, 320 float4
        for (int idx = tid; idx < BK * (BN / 4); idx += 128) {
            int r = idx / (BN / 4);      // 0..19
            int c4 = idx % (BN / 4);     // 0..15
            int n = n0 + c4 * 4;
            float4 v = make_float4(0.f, 0.f, 0.f, 0.f);
            if (n < N) v = *(const float4*)&B[(long)(k0 + r) * N + n];
            *(float4*)&Bs[r][c4 * 4] = v;
        }
        __syncthreads();

        #pragma unroll
        for (int k = 0; k < BK; k++) {
            float4 a0 = *(const float4*)&As[k][ty * 8];
            float4 a1 = *(const float4*)&As[k][ty * 8 + 4];
            float4 b0 = *(const float4*)&Bs[k][tx * 8];
            float4 b1 = *(const float4*)&Bs[k][tx * 8 + 4];
            float ra[8] = {a0.x, a0.y, a0.z, a0.w, a1.x, a1.y, a1.z, a1.w};
            float rb[8] = {b0.x, b0.y, b0.z, b0.w, b1.x, b1.y, b1.z, b1.w};
            #pragma unroll
            for (int i = 0; i < 8; i++)
                #pragma unroll
                for (int j = 0; j < 8; j++) acc[i][j] += ra[i] * rb[j];
        }
        __syncthreads();
    }

    #pragma unroll
    for (int i = 0; i < 8; i++) {
        long m = m0 + ty * 8 + i;
        #pragma unroll
        for (int j4 = 0; j4 < 2; j4++) {
            int n = n0 + tx * 8 + j4 * 4;
            if (n < N)
                *(float4*)&C[m * N + n] = make_float4(acc[i][j4 * 4 + 0],
                                                      acc[i][j4 * 4 + 1],
                                                      acc[i][j4 * 4 + 2],
                                                      acc[i][j4 * 4 + 3]);
        }
    }
}

// ---------------- K3/K5: batched adjacency GEMM + fused epilogue ----------------
// out[b,t,:] = relu((A_b @ Y_b + Y_b[t,:] + add) / denom[b,t])
// BM=BN=64, BK=20, 64 threads, 8x8 per-thread, float4 paths.
__global__ __launch_bounds__(64)
void k_adjgemm_v2(const int* __restrict__ adj, const float* __restrict__ Y,
                  const float* __restrict__ addv, const float* __restrict__ bias,
                  float* __restrict__ out) {
    const int BM = 64, BN = 64, BK = 20;
    __shared__ float As[BK][BM + 4];
    __shared__ float Bs[BK][BN];

    int b = blockIdx.z;
    const int*   Ab = adj + (long)b * TT * TT;
    const float* Yb = Y + (long)b * TT * MEM;

    int tid = threadIdx.x;     // 64
    int tx = tid & 7;          // 0..7
    int ty = tid >> 3;         // 0..7
    int m0 = blockIdx.y * BM;
    int n0 = blockIdx.x * BN;

    float acc[8][8];
    #pragma unroll
    for (int i = 0; i < 8; i++)
        #pragma unroll
        for (int j = 0; j < 8; j++) acc[i][j] = 0.0f;

    for (int k0 = 0; k0 < TT; k0 += BK) {
        // A tile: 64x20 ints -> float, transposed; 320 int4, 5/thread
        #pragma unroll
        for (int i = 0; i < 5; i++) {
            int idx = tid + i * 64;
            int r = idx / (BK / 4);      // 0..63
            int c4 = idx % (BK / 4);     // 0..4
            int4 v = make_int4(0, 0, 0, 0);
            if (m0 + r < TT) v = *(const int4*)&Ab[(m0 + r) * TT + k0 + c4 * 4];
            As[c4 * 4 + 0][r] = (float)v.x;
            As[c4 * 4 + 1][r] = (float)v.y;
            As[c4 * 4 + 2][r] = (float)v.z;
            As[c4 * 4 + 3][r] = (float)v.w;
        }
        // Y tile: 20x64 floats; 320 float4, 5/thread
        #pragma unroll
        for (int i = 0; i < 5; i++) {
            int idx = tid + i * 64;
            int r = idx / (BN / 4);      // 0..19
            int c4 = idx % (BN / 4);     // 0..15
            int n = n0 + c4 * 4;
            float4 v = make_float4(0.f, 0.f, 0.f, 0.f);
            if (n < MEM) v = *(const float4*)&Yb[(k0 + r) * MEM + n];
            *(float4*)&Bs[r][c4 * 4] = v;
        }
        __syncthreads();

        #pragma unroll
        for (int k = 0; k < BK; k++) {
            float4 a0 = *(const float4*)&As[k][ty * 8];
            float4 a1 = *(const float4*)&As[k][ty * 8 + 4];
            float4 b0 = *(const float4*)&Bs[k][tx * 8];
            float4 b1 = *(const float4*)&Bs[k][tx * 8 + 4];
            float ra[8] = {a0.x, a0.y, a0.z, a0.w, a1.x, a1.y, a1.z, a1.w};
            float rb[8] = {b0.x, b0.y, b0.z, b0.w, b1.x, b1.y, b1.z, b1.w};
            #pragma unroll
            for (int i = 0; i < 8; i++)
                #pragma unroll
                for (int j = 0; j < 8; j++) acc[i][j] += ra[i] * rb[j];
        }
        __syncthreads();
    }

    #pragma unroll
    for (int i = 0; i < 8; i++) {
        int t = m0 + ty * 8 + i;
        if (t >= TT) continue;
        float rd = g_rd[b * TT + t];
        long rowbase = ((long)b * TT + t) * MEM;
        #pragma unroll
        for (int j4 = 0; j4 < 2; j4++) {
            int n = n0 + tx * 8 + j4 * 4;
            if (n >= MEM) continue;
            float4 yv = *(const float4*)&Yb[t * MEM + n];
            float4 av;
            if (addv) av = *(const float4*)&addv[rowbase + n];
            else      av = make_float4(2.f * bias[n], 2.f * bias[n + 1],
                                       2.f * bias[n + 2], 2.f * bias[n + 3]);
            float4 o;
            o.x = (acc[i][j4 * 4 + 0] + yv.x + av.x) * rd;
            o.y = (acc[i][j4 * 4 + 1] + yv.y + av.y) * rd;
            o.z = (acc[i][j4 * 4 + 2] + yv.z + av.z) * rd;
            o.w = (acc[i][j4 * 4 + 3] + yv.w + av.w) * rd;
            o.x = o.x > 0.f ? o.x : 0.f;
            o.y = o.y > 0.f ? o.y : 0.f;
            o.z = o.z > 0.f ? o.z : 0.f;
            o.w = o.w > 0.f ? o.w : 0.f;
            *(float4*)&out[rowbase + n] = o;
        }
    }
}

// ---------------- launch ----------------
extern "C" void kernel_launch(void* const* d_in, const int* in_sizes, int n_in,
                              void* d_out, int out_size) {
    const int*   adj      = (const int*)d_in[0];
    const int*   words    = (const int*)d_in[1];
    const int*   pos      = (const int*)d_in[2];
    const int*   ner      = (const int*)d_in[3];
    const int*   dep_ids  = (const int*)d_in[4];
    const int*   dep_mask = (const int*)d_in[5];
    // d_in[6] = maxlen (compile-time TT)
    const float* wemb = (const float*)d_in[7];
    const float* pemb = (const float*)d_in[8];
    const float* nemb = (const float*)d_in[9];
    const float* demb = (const float*)d_in[10];
    const float* W0w  = (const float*)d_in[11];
    const float* W0b  = (const float*)d_in[12];
    const float* W1w  = (const float*)d_in[13];
    const float* W1b  = (const float*)d_in[14];
    float* out = (float*)d_out;

    float *px, *py, *pc, *ph, *pz;
    cudaGetSymbolAddress((void**)&px, g_x);
    cudaGetSymbolAddress((void**)&py, g_y);
    cudaGetSymbolAddress((void**)&pc, g_c);
    cudaGetSymbolAddress((void**)&ph, g_h);
    cudaGetSymbolAddress((void**)&pz, g_z);

    int write_mask = (out_size >= (int)(BT * MEM + BT));

    // K0: denoms + output mask
    k_prep<<<BATCH, 256>>>(adj, out, write_mask);

    // K1: gather x, build c
    k_embed<<<(int)BT, 384>>>(words, pos, ner, dep_ids, dep_mask,
                              wemb, pemb, nemb, demb, W0w, W0b);

    // K2: y = x @ W0a  (M=51200, K=360, N=300)
    {
        dim3 grid((MEM + 63) / 64, (int)(BT / 128));
        k_gemm_v2<<<grid, 128>>>(px, W0w, py, (int)BT, MEM, INX);
    }

    // K3: h = relu((A@y + y + c)/denom)
    {
        dim3 grid((MEM + 63) / 64, (TT + 63) / 64, BATCH);
        k_adjgemm_v2<<<grid, 64>>>(adj, py, pc, nullptr, ph);
    }

    // K4: z = h @ W1  (M=51200, K=300, N=300)
    {
        dim3 grid((MEM + 63) / 64, (int)(BT / 128));
        k_gemm_v2<<<grid, 128>>>(ph, W1w, pz, (int)BT, MEM, MEM);
    }

    // K5: out = relu((A@z + z + 2*b1)/denom)
    {
        dim3 grid((MEM + 63) / 64, (TT + 63) / 64, BATCH);
        k_adjgemm_v2<<<grid, 64>>>(adj, pz, nullptr, W1b, out);
    }
}

// round 5
// speedup vs baseline: 1.9085x; 1.6252x over previous
#include <cuda_runtime.h>
#include <cuda_bf16.h>
#include <cstdint>

// ---------------- problem constants ----------------
#define BATCH 256
#define TT    200
#define EMBD  300
#define PD    30
#define MEM   300
#define KDEP  5
#define KP0   384     // padded K, layer-0 dense (360 -> 384)
#define KP1   320     // padded K, layer-1 dense (300 -> 320)
#define NP    320     // padded N (300 -> 320)
#define SP    224     // padded sequence (K of adjacency GEMM, 200 -> 224)

constexpr long BT = (long)BATCH * TT;   // 51200

// ---------------- scratch (device globals; zero-initialized at load) ----------------
// Padding regions are never written by any kernel -> stay zero across replays.
__device__ __nv_bfloat16 g_xh[BT * KP0], g_xl[BT * KP0];             // x split [bt][384]
__device__ __nv_bfloat16 g_hh[BT * KP1], g_hl[BT * KP1];             // h split [bt][320]
__device__ __nv_bfloat16 g_yh[(long)BATCH * SP * NP], g_yl[(long)BATCH * SP * NP]; // y [b][s][n]
__device__ __nv_bfloat16 g_zh[(long)BATCH * SP * NP], g_zl[(long)BATCH * SP * NP]; // z [b][s][n]
__device__ __nv_bfloat16 g_ab[(long)BATCH * TT * SP];                // (A+I) bf16 [b][t][s]
__device__ __nv_bfloat16 g_w0h[NP * KP0], g_w0l[NP * KP0];           // W0a^T split [320][384]
__device__ __nv_bfloat16 g_w1h[NP * KP1], g_w1l[NP * KP1];           // W1^T  split [320][320]
__device__ float g_c[BT * MEM];                                      // dep contribution
__device__ float g_rd[BT];                                           // 1/denom

// ---------------- helpers ----------------
__device__ __forceinline__ uint32_t smem_u32(const void* p) {
    return (uint32_t)__cvta_generic_to_shared(p);
}
__device__ __forceinline__ void bsplit(float v, __nv_bfloat16& h, __nv_bfloat16& l) {
    h = __float2bfloat16(v);
    l = __float2bfloat16(v - __bfloat162float(h));
}
__device__ __forceinline__ uint32_t bpack(__nv_bfloat16 a, __nv_bfloat16 b) {
    return (uint32_t)__bfloat16_as_ushort(a) | ((uint32_t)__bfloat16_as_ushort(b) << 16);
}
__device__ __forceinline__ void ldm_x4(uint32_t (&r)[4], uint32_t addr) {
    asm volatile("ldmatrix.sync.aligned.m8n8.x4.shared.b16 {%0,%1,%2,%3}, [%4];"
                 : "=r"(r[0]), "=r"(r[1]), "=r"(r[2]), "=r"(r[3]) : "r"(addr));
}
__device__ __forceinline__ void ldm_x2(uint32_t (&r)[2], uint32_t addr) {
    asm volatile("ldmatrix.sync.aligned.m8n8.x2.shared.b16 {%0,%1}, [%2];"
                 : "=r"(r[0]), "=r"(r[1]) : "r"(addr));
}
__device__ __forceinline__ void ldm_x2t(uint32_t (&r)[2], uint32_t addr) {
    asm volatile("ldmatrix.sync.aligned.m8n8.x2.trans.shared.b16 {%0,%1}, [%2];"
                 : "=r"(r[0]), "=r"(r[1]) : "r"(addr));
}
__device__ __forceinline__ void mma_bf16(float (&d)[4], const uint32_t (&a)[4],
                                         const uint32_t (&b)[2]) {
    asm volatile(
        "mma.sync.aligned.m16n8k16.row.col.f32.bf16.bf16.f32 "
        "{%0,%1,%2,%3}, {%4,%5,%6,%7}, {%8,%9}, {%0,%1,%2,%3};"
        : "+f"(d[0]), "+f"(d[1]), "+f"(d[2]), "+f"(d[3])
        : "r"(a[0]), "r"(a[1]), "r"(a[2]), "r"(a[3]), "r"(b[0]), "r"(b[1]));
}

// ---------------- K0: row/col sums of A -> 1/denom, out_mask ----------------
__global__ void k_prep(const int* __restrict__ adj, float* __restrict__ out,
                       int write_mask) {
    int b = blockIdx.x;
    const int* Ab = adj + (long)b * TT * TT;
    int t = threadIdx.x;

    __shared__ int rows[TT];
    for (int i = t; i < TT; i += blockDim.x) rows[i] = 0;
    __syncthreads();

    int cs = 0;
    for (int s = 0; s < TT; s++) {
        int v = (t < TT) ? Ab[s * TT + t] : 0;
        cs += v;
        #pragma unroll
        for (int o = 16; o > 0; o >>= 1) v += __shfl_down_sync(0xffffffff, v, o);
        if ((threadIdx.x & 31) == 0) atomicAdd(&rows[s], v);
    }
    __syncthreads();

    if (t < TT) {
        int rs = rows[t];
        g_rd[b * TT + t] = 1.0f / (float)(rs + 1);
        if (write_mask)
            out[BT * MEM + (long)b * TT + t] = (rs + cs == 0) ? 1.0f : 0.0f;
    }
}

// ---------------- K0b: adjacency + I -> bf16, [b][t][224] ----------------
__global__ void k_adjconv(const int* __restrict__ adj) {
    long idx = (long)blockIdx.x * 256 + threadIdx.x;     // one int4 (4 cols) each
    // total = BATCH*TT*(TT/4) = 2,560,000
    int s4 = (int)(idx % (TT / 4)) * 4;
    long bt = idx / (TT / 4);
    int t = (int)(bt % TT);
    int4 v = *(const int4*)(adj + bt * TT + s4);
    float f0 = (float)v.x, f1 = (float)v.y, f2 = (float)v.z, f3 = (float)v.w;
    int dd = t - s4;
    if (dd >= 0 && dd < 4) {
        if (dd == 0) f0 += 1.0f; else if (dd == 1) f1 += 1.0f;
        else if (dd == 2) f2 += 1.0f; else f3 += 1.0f;
    }
    uint2 p;
    p.x = bpack(__float2bfloat16(f0), __float2bfloat16(f1));
    p.y = bpack(__float2bfloat16(f2), __float2bfloat16(f3));
    *(uint2*)&g_ab[bt * SP + s4] = p;
}

// ---------------- K1: embedding gather (split bf16) + dep vector c ----------------
__global__ void k_embed(const int* __restrict__ words, const int* __restrict__ pos,
                        const int* __restrict__ ner, const int* __restrict__ dep_ids,
                        const int* __restrict__ dep_mask,
                        const float* __restrict__ wemb, const float* __restrict__ pemb,
                        const float* __restrict__ nemb, const float* __restrict__ demb,
                        const float* __restrict__ W0w, const float* __restrict__ W0b) {
    long bt = blockIdx.x;
    int tid = threadIdx.x;
    __shared__ float sg[PD];

    float v = 0.0f;
    bool have = false;
    if (tid < EMBD) { v = wemb[(long)words[bt] * EMBD + tid]; have = true; }
    else if (tid < EMBD + PD) { v = pemb[pos[bt] * PD + (tid - EMBD)]; have = true; }
    else if (tid < EMBD + 2 * PD) { v = nemb[ner[bt] * PD + (tid - EMBD - PD)]; have = true; }
    if (have) {
        __nv_bfloat16 h, l; bsplit(v, h, l);
        g_xh[bt * KP0 + tid] = h;
        g_xl[bt * KP0 + tid] = l;
    }

    if (tid < PD) {
        float s = 0.0f;
        int any = 0;
        #pragma unroll
        for (int j = 0; j < KDEP; j++) {
            int m  = dep_mask[bt * KDEP + j];
            int id = dep_ids[bt * KDEP + j];
            any += m;
            s += m ? demb[id * PD + tid] : 0.0f;
        }
        if (any == 0) s = demb[tid];
        sg[tid] = s + demb[PD + tid];
    }
    __syncthreads();

    if (tid < MEM) {
        const float* Wd = W0w + (long)(EMBD + 2 * PD) * MEM;   // rows 360..389
        float acc = 2.0f * W0b[tid];
        #pragma unroll
        for (int k = 0; k < PD; k++) acc += sg[k] * Wd[k * MEM + tid];
        g_c[bt * MEM + tid] = acc;
    }
}

// ---------------- K1b: transpose + split + pad the weight matrices ----------------
__global__ void k_wsplit(const float* __restrict__ W0, const float* __restrict__ W1) {
    int idx = blockIdx.x * 256 + threadIdx.x;
    if (idx < NP * KP0) {
        int n = idx / KP0, k = idx % KP0;
        float v = (n < MEM && k < EMBD + 2 * PD) ? W0[(long)k * MEM + n] : 0.0f;
        __nv_bfloat16 h, l; bsplit(v, h, l);
        g_w0h[idx] = h; g_w0l[idx] = l;
    }
    if (idx < NP * KP1) {
        int n = idx / KP1, k = idx % KP1;
        float v = (n < MEM && k < MEM) ? W1[(long)k * MEM + n] : 0.0f;
        __nv_bfloat16 h, l; bsplit(v, h, l);
        g_w1h[idx] = h; g_w1l[idx] = l;
    }
}

// ---------------- dense GEMM: y[b][s][n] = (x @ W^T), split-bf16, mma.sync ----------------
// A [BT,KPAD] k-major hi/lo; W^T [NP,KPAD] k-major hi/lo; out natural [b][SP][NP] hi/lo.
// CTA 128x64, 4 warps (2m x 2n), warp tile 64x32, BK=32.
template <int KPAD>
__global__ __launch_bounds__(128)
void k_dense(const __nv_bfloat16* __restrict__ Ah, const __nv_bfloat16* __restrict__ Al,
             const __nv_bfloat16* __restrict__ Wh, const __nv_bfloat16* __restrict__ Wl,
             __nv_bfloat16* __restrict__ Yh, __nv_bfloat16* __restrict__ Yl) {
    __shared__ __nv_bfloat16 sAh[128 * 40], sAl[128 * 40];
    __shared__ __nv_bfloat16 sBh[64 * 40],  sBl[64 * 40];

    int tid = threadIdx.x, lane = tid & 31, wid = tid >> 5;
    int wm = wid >> 1, wn = wid & 1;
    long m0 = (long)blockIdx.y * 128;
    int  n0 = blockIdx.x * 64;

    uint32_t uAh = smem_u32(sAh), uAl = smem_u32(sAl);
    uint32_t uBh = smem_u32(sBh), uBl = smem_u32(sBl);

    float acc[4][4][4];
    #pragma unroll
    for (int i = 0; i < 4; i++)
        #pragma unroll
        for (int j = 0; j < 4; j++)
            #pragma unroll
            for (int q = 0; q < 4; q++) acc[i][j][q] = 0.0f;

    for (int k0 = 0; k0 < KPAD; k0 += 32) {
        #pragma unroll
        for (int i = 0; i < 4; i++) {
            int idx = tid + i * 128;
            int r = idx >> 2, g = idx & 3;
            *(uint4*)&sAh[r * 40 + g * 8] = *(const uint4*)&Ah[(m0 + r) * KPAD + k0 + g * 8];
            *(uint4*)&sAl[r * 40 + g * 8] = *(const uint4*)&Al[(m0 + r) * KPAD + k0 + g * 8];
        }
        #pragma unroll
        for (int i = 0; i < 2; i++) {
            int idx = tid + i * 128;
            int r = idx >> 2, g = idx & 3;
            *(uint4*)&sBh[r * 40 + g * 8] = *(const uint4*)&Wh[(long)(n0 + r) * KPAD + k0 + g * 8];
            *(uint4*)&sBl[r * 40 + g * 8] = *(const uint4*)&Wl[(long)(n0 + r) * KPAD + k0 + g * 8];
        }
        __syncthreads();

        #pragma unroll
        for (int ks = 0; ks < 32; ks += 16) {
            uint32_t ah[4][4], al[4][4], bh[4][2], bl[4][2];
            #pragma unroll
            for (int mi = 0; mi < 4; mi++) {
                uint32_t off = (uint32_t)(((wm * 64 + mi * 16 + (lane & 15)) * 40 +
                                           ks + ((lane >> 4) << 3)) * 2);
                ldm_x4(ah[mi], uAh + off);
                ldm_x4(al[mi], uAl + off);
            }
            #pragma unroll
            for (int ni = 0; ni < 4; ni++) {
                uint32_t off = (uint32_t)(((wn * 32 + ni * 8 + (lane & 7)) * 40 +
                                           ks + (((lane >> 3) & 1) << 3)) * 2);
                ldm_x2(bh[ni], uBh + off);
                ldm_x2(bl[ni], uBl + off);
            }
            #pragma unroll
            for (int mi = 0; mi < 4; mi++)
                #pragma unroll
                for (int ni = 0; ni < 4; ni++) {
                    mma_bf16(acc[mi][ni], ah[mi], bh[ni]);
                    mma_bf16(acc[mi][ni], ah[mi], bl[ni]);
                    mma_bf16(acc[mi][ni], al[mi], bh[ni]);
                }
        }
        __syncthreads();
    }

    // epilogue: write y split bf16, natural [b][s][n], packed-pair stores
    #pragma unroll
    for (int mi = 0; mi < 4; mi++) {
        #pragma unroll
        for (int half = 0; half < 2; half++) {
            long row = m0 + wm * 64 + mi * 16 + (lane >> 2) + half * 8;
            long b = row / TT;
            int  s = (int)(row % TT);
            long base = (b * SP + s) * NP;
            #pragma unroll
            for (int ni = 0; ni < 4; ni++) {
                int n = n0 + wn * 32 + ni * 8 + (lane & 3) * 2;
                float v0 = acc[mi][ni][half * 2 + 0];
                float v1 = acc[mi][ni][half * 2 + 1];
                __nv_bfloat16 h0, l0, h1, l1;
                bsplit(v0, h0, l0); bsplit(v1, h1, l1);
                *(uint32_t*)&Yh[base + n] = bpack(h0, h1);
                *(uint32_t*)&Yl[base + n] = bpack(l0, l1);
            }
        }
    }
}

// ---------------- adjacency GEMM: D = (A+I) @ y, fused epilogue ----------------
// A: g_ab bf16 [b][t][SP] exact; B: y [b][s][n] hi/lo (ldmatrix.trans).
// layer0: h = relu((D + c) * rd) -> split bf16 [bt][320]
// layer1: out = relu((D + 2*bias) * rd) -> fp32 [bt][300]
__global__ __launch_bounds__(128)
void k_adj(const __nv_bfloat16* __restrict__ Yh, const __nv_bfloat16* __restrict__ Yl,
           const float* __restrict__ cvec, const float* __restrict__ bias,
           __nv_bfloat16* __restrict__ Hh, __nv_bfloat16* __restrict__ Hl,
           float* __restrict__ outp, int layer0) {
    __shared__ __nv_bfloat16 sA[128 * 40];
    __shared__ __nv_bfloat16 sYh[32 * 72], sYl[32 * 72];

    int tid = threadIdx.x, lane = tid & 31, wid = tid >> 5;
    int wm = wid >> 1, wn = wid & 1;
    int b  = blockIdx.z;
    int m0 = blockIdx.y * 72;       // 0 or 72 (tiles overlap; identical values)
    int n0 = blockIdx.x * 64;

    uint32_t uA = smem_u32(sA), uYh = smem_u32(sYh), uYl = smem_u32(sYl);

    float acc[4][4][4];
    #pragma unroll
    for (int i = 0; i < 4; i++)
        #pragma unroll
        for (int j = 0; j < 4; j++)
            #pragma unroll
            for (int q = 0; q < 4; q++) acc[i][j][q] = 0.0f;

    for (int k0 = 0; k0 < SP; k0 += 32) {
        #pragma unroll
        for (int i = 0; i < 4; i++) {
            int idx = tid + i * 128;
            int r = idx >> 2, g = idx & 3;
            *(uint4*)&sA[r * 40 + g * 8] =
                *(const uint4*)&g_ab[((long)b * TT + m0 + r) * SP + k0 + g * 8];
        }
        #pragma unroll
        for (int i = 0; i < 2; i++) {
            int idx = tid + i * 128;
            int r = idx >> 3, g = idx & 7;     // r: 0..31 (s), g: 0..7 (n seg)
            long gb = ((long)b * SP + k0 + r) * NP + n0 + g * 8;
            *(uint4*)&sYh[r * 72 + g * 8] = *(const uint4*)&Yh[gb];
            *(uint4*)&sYl[r * 72 + g * 8] = *(const uint4*)&Yl[gb];
        }
        __syncthreads();

        #pragma unroll
        for (int ks = 0; ks < 32; ks += 16) {
            uint32_t aa[4][4], bh[4][2], bl[4][2];
            #pragma unroll
            for (int mi = 0; mi < 4; mi++) {
                uint32_t off = (uint32_t)(((wm * 64 + mi * 16 + (lane & 15)) * 40 +
                                           ks + ((lane >> 4) << 3)) * 2);
                ldm_x4(aa[mi], uA + off);
            }
            #pragma unroll
            for (int ni = 0; ni < 4; ni++) {
                uint32_t off = (uint32_t)(((ks + (lane & 15)) * 72 +
                                           wn * 32 + ni * 8) * 2);
                ldm_x2t(bh[ni], uYh + off);
                ldm_x2t(bl[ni], uYl + off);
            }
            #pragma unroll
            for (int mi = 0; mi < 4; mi++)
                #pragma unroll
                for (int ni = 0; ni < 4; ni++) {
                    mma_bf16(acc[mi][ni], aa[mi], bh[ni]);
                    mma_bf16(acc[mi][ni], aa[mi], bl[ni]);
                }
        }
        __syncthreads();
    }

    // fused epilogue
    #pragma unroll
    for (int mi = 0; mi < 4; mi++) {
        #pragma unroll
        for (int half = 0; half < 2; half++) {
            int t = m0 + wm * 64 + mi * 16 + (lane >> 2) + half * 8;   // < 200
            long bt = (long)b * TT + t;
            float rd = g_rd[bt];
            #pragma unroll
            for (int ni = 0; ni < 4; ni++) {
                int n = n0 + wn * 32 + ni * 8 + (lane & 3) * 2;
                if (n >= MEM) continue;
                float a0, a1;
                if (layer0) { a0 = cvec[bt * MEM + n]; a1 = cvec[bt * MEM + n + 1]; }
                else        { a0 = 2.0f * bias[n];     a1 = 2.0f * bias[n + 1]; }
                float v0 = (acc[mi][ni][half * 2 + 0] + a0) * rd;
                float v1 = (acc[mi][ni][half * 2 + 1] + a1) * rd;
                v0 = v0 > 0.0f ? v0 : 0.0f;
                v1 = v1 > 0.0f ? v1 : 0.0f;
                if (layer0) {
                    __nv_bfloat16 h0, l0, h1, l1;
                    bsplit(v0, h0, l0); bsplit(v1, h1, l1);
                    *(uint32_t*)&Hh[bt * KP1 + n] = bpack(h0, h1);
                    *(uint32_t*)&Hl[bt * KP1 + n] = bpack(l0, l1);
                } else {
                    *(float2*)&outp[bt * MEM + n] = make_float2(v0, v1);
                }
            }
        }
    }
}

// ---------------- launch ----------------
extern "C" void kernel_launch(void* const* d_in, const int* in_sizes, int n_in,
                              void* d_out, int out_size) {
    const int*   adj      = (const int*)d_in[0];
    const int*   words    = (const int*)d_in[1];
    const int*   pos      = (const int*)d_in[2];
    const int*   ner      = (const int*)d_in[3];
    const int*   dep_ids  = (const int*)d_in[4];
    const int*   dep_mask = (const int*)d_in[5];
    const float* wemb = (const float*)d_in[7];
    const float* pemb = (const float*)d_in[8];
    const float* nemb = (const float*)d_in[9];
    const float* demb = (const float*)d_in[10];
    const float* W0w  = (const float*)d_in[11];
    const float* W0b  = (const float*)d_in[12];
    const float* W1w  = (const float*)d_in[13];
    const float* W1b  = (const float*)d_in[14];
    float* out = (float*)d_out;

    __nv_bfloat16 *xh, *xl, *hh, *hl, *yh, *yl, *zh, *zl, *w0h, *w0l, *w1h, *w1l;
    float* pc;
    cudaGetSymbolAddress((void**)&xh,  g_xh);  cudaGetSymbolAddress((void**)&xl,  g_xl);
    cudaGetSymbolAddress((void**)&hh,  g_hh);  cudaGetSymbolAddress((void**)&hl,  g_hl);
    cudaGetSymbolAddress((void**)&yh,  g_yh);  cudaGetSymbolAddress((void**)&yl,  g_yl);
    cudaGetSymbolAddress((void**)&zh,  g_zh);  cudaGetSymbolAddress((void**)&zl,  g_zl);
    cudaGetSymbolAddress((void**)&w0h, g_w0h); cudaGetSymbolAddress((void**)&w0l, g_w0l);
    cudaGetSymbolAddress((void**)&w1h, g_w1h); cudaGetSymbolAddress((void**)&w1l, g_w1l);
    cudaGetSymbolAddress((void**)&pc,  g_c);

    int write_mask = (out_size >= (int)(BT * MEM + BT));

    k_prep<<<BATCH, 256>>>(adj, out, write_mask);
    k_adjconv<<<(int)((long)BATCH * TT * (TT / 4) / 256), 256>>>(adj);
    k_embed<<<(int)BT, 384>>>(words, pos, ner, dep_ids, dep_mask,
                              wemb, pemb, nemb, demb, W0w, W0b);
    k_wsplit<<<(NP * KP0 + 255) / 256, 256>>>(W0w, W1w);

    dim3 gd(NP / 64, (int)(BT / 128));         // (5, 400)
    dim3 ga(NP / 64, 2, BATCH);                // (5, 2, 256)

    // layer 0
    k_dense<KP0><<<gd, 128>>>(xh, xl, w0h, w0l, yh, yl);
    k_adj<<<ga, 128>>>(yh, yl, pc, nullptr, hh, hl, nullptr, 1);

    // layer 1
    k_dense<KP1><<<gd, 128>>>(hh, hl, w1h, w1l, zh, zl);
    k_adj<<<ga, 128>>>(zh, zl, nullptr, W1b, nullptr, nullptr, out, 0);
}

// round 7
// speedup vs baseline: 2.0851x; 1.0925x over previous
#include <cuda_runtime.h>
#include <cuda_bf16.h>
#include <cstdint>

// ---------------- problem constants ----------------
#define BATCH 256
#define TT    200
#define EMBD  300
#define PD    30
#define MEM   300
#define KDEP  5
#define KP0   384     // padded K, layer-0 dense (360 -> 384)
#define KP1   320     // padded K, layer-1 dense (300 -> 320)
#define NP    320     // padded N (300 -> 320)
#define SP    224     // padded sequence (K of adjacency GEMM, 200 -> 224)

constexpr long BT = (long)BATCH * TT;   // 51200

// ---------------- scratch (device globals; zero-initialized at load) ----------------
__device__ __nv_bfloat16 g_xh[BT * KP0], g_xl[BT * KP0];             // x split [bt][384]
__device__ __nv_bfloat16 g_hh[BT * KP1], g_hl[BT * KP1];             // h split [bt][320]
__device__ __nv_bfloat16 g_yh[(long)BATCH * SP * NP], g_yl[(long)BATCH * SP * NP]; // y [b][s][n]
__device__ __nv_bfloat16 g_zh[(long)BATCH * SP * NP], g_zl[(long)BATCH * SP * NP]; // z [b][s][n]
__device__ __nv_bfloat16 g_ab[(long)BATCH * TT * SP];                // (A+I) bf16 [b][t][s]
__device__ __nv_bfloat16 g_w0h[NP * KP0], g_w0l[NP * KP0];           // W0a^T split [320][384]
__device__ __nv_bfloat16 g_w1h[NP * KP1], g_w1l[NP * KP1];           // W1^T  split [320][320]
__device__ float g_c[BT * MEM];                                      // dep contribution
__device__ float g_rd[BT];                                           // 1/denom

// ---------------- helpers ----------------
__device__ __forceinline__ uint32_t smem_u32(const void* p) {
    return (uint32_t)__cvta_generic_to_shared(p);
}
__device__ __forceinline__ void bsplit(float v, __nv_bfloat16& h, __nv_bfloat16& l) {
    h = __float2bfloat16(v);
    l = __float2bfloat16(v - __bfloat162float(h));
}
__device__ __forceinline__ uint32_t bpack(__nv_bfloat16 a, __nv_bfloat16 b) {
    return (uint32_t)__bfloat16_as_ushort(a) | ((uint32_t)__bfloat16_as_ushort(b) << 16);
}
__device__ __forceinline__ void cp16(uint32_t dst, const void* src) {
    asm volatile("cp.async.cg.shared.global [%0], [%1], 16;" :: "r"(dst), "l"(src));
}
__device__ __forceinline__ void cp_commit() {
    asm volatile("cp.async.commit_group;" ::: "memory");
}
template <int N>
__device__ __forceinline__ void cp_wait() {
    asm volatile("cp.async.wait_group %0;" :: "n"(N) : "memory");
}
__device__ __forceinline__ void ldm_x4(uint32_t (&r)[4], uint32_t addr) {
    asm volatile("ldmatrix.sync.aligned.m8n8.x4.shared.b16 {%0,%1,%2,%3}, [%4];"
                 : "=r"(r[0]), "=r"(r[1]), "=r"(r[2]), "=r"(r[3]) : "r"(addr));
}
__device__ __forceinline__ void ldm_x2(uint32_t (&r)[2], uint32_t addr) {
    asm volatile("ldmatrix.sync.aligned.m8n8.x2.shared.b16 {%0,%1}, [%2];"
                 : "=r"(r[0]), "=r"(r[1]) : "r"(addr));
}
__device__ __forceinline__ void ldm_x2t(uint32_t (&r)[2], uint32_t addr) {
    asm volatile("ldmatrix.sync.aligned.m8n8.x2.trans.shared.b16 {%0,%1}, [%2];"
                 : "=r"(r[0]), "=r"(r[1]) : "r"(addr));
}
__device__ __forceinline__ void mma_bf16(float (&d)[4], const uint32_t (&a)[4],
                                         const uint32_t (&b)[2]) {
    asm volatile(
        "mma.sync.aligned.m16n8k16.row.col.f32.bf16.bf16.f32 "
        "{%0,%1,%2,%3}, {%4,%5,%6,%7}, {%8,%9}, {%0,%1,%2,%3};"
        : "+f"(d[0]), "+f"(d[1]), "+f"(d[2]), "+f"(d[3])
        : "r"(a[0]), "r"(a[1]), "r"(a[2]), "r"(a[3]), "r"(b[0]), "r"(b[1]));
}

// ---------------- K0: row/col sums of A -> 1/denom, out_mask ----------------
__global__ void k_prep(const int* __restrict__ adj, float* __restrict__ out,
                       int write_mask) {
    int b = blockIdx.x;
    const int* Ab = adj + (long)b * TT * TT;
    int t = threadIdx.x;

    __shared__ int rows[TT];
    for (int i = t; i < TT; i += blockDim.x) rows[i] = 0;
    __syncthreads();

    int cs = 0;
    for (int s = 0; s < TT; s++) {
        int v = (t < TT) ? Ab[s * TT + t] : 0;
        cs += v;
        #pragma unroll
        for (int o = 16; o > 0; o >>= 1) v += __shfl_down_sync(0xffffffff, v, o);
        if ((threadIdx.x & 31) == 0) atomicAdd(&rows[s], v);
    }
    __syncthreads();

    if (t < TT) {
        int rs = rows[t];
        g_rd[b * TT + t] = 1.0f / (float)(rs + 1);
        if (write_mask)
            out[BT * MEM + (long)b * TT + t] = (rs + cs == 0) ? 1.0f : 0.0f;
    }
}

// ---------------- K0b: adjacency + I -> bf16, [b][t][224] ----------------
__global__ void k_adjconv(const int* __restrict__ adj) {
    long idx = (long)blockIdx.x * 256 + threadIdx.x;     // one int4 (4 cols) each
    int s4 = (int)(idx % (TT / 4)) * 4;
    long bt = idx / (TT / 4);
    int t = (int)(bt % TT);
    int4 v = *(const int4*)(adj + bt * TT + s4);
    float f0 = (float)v.x, f1 = (float)v.y, f2 = (float)v.z, f3 = (float)v.w;
    int dd = t - s4;
    if (dd >= 0 && dd < 4) {
        if (dd == 0) f0 += 1.0f; else if (dd == 1) f1 += 1.0f;
        else if (dd == 2) f2 += 1.0f; else f3 += 1.0f;
    }
    uint2 p;
    p.x = bpack(__float2bfloat16(f0), __float2bfloat16(f1));
    p.y = bpack(__float2bfloat16(f2), __float2bfloat16(f3));
    *(uint2*)&g_ab[bt * SP + s4] = p;
}

// ---------------- K1: embedding gather (split bf16) + dep vector c ----------------
__global__ void k_embed(const int* __restrict__ words, const int* __restrict__ pos,
                        const int* __restrict__ ner, const int* __restrict__ dep_ids,
                        const int* __restrict__ dep_mask,
                        const float* __restrict__ wemb, const float* __restrict__ pemb,
                        const float* __restrict__ nemb, const float* __restrict__ demb,
                        const float* __restrict__ W0w, const float* __restrict__ W0b) {
    long bt = blockIdx.x;
    int tid = threadIdx.x;
    __shared__ float sg[PD];

    float v = 0.0f;
    bool have = false;
    if (tid < EMBD) { v = wemb[(long)words[bt] * EMBD + tid]; have = true; }
    else if (tid < EMBD + PD) { v = pemb[pos[bt] * PD + (tid - EMBD)]; have = true; }
    else if (tid < EMBD + 2 * PD) { v = nemb[ner[bt] * PD + (tid - EMBD - PD)]; have = true; }
    if (have) {
        __nv_bfloat16 h, l; bsplit(v, h, l);
        g_xh[bt * KP0 + tid] = h;
        g_xl[bt * KP0 + tid] = l;
    }

    if (tid < PD) {
        float s = 0.0f;
        int any = 0;
        #pragma unroll
        for (int j = 0; j < KDEP; j++) {
            int m  = dep_mask[bt * KDEP + j];
            int id = dep_ids[bt * KDEP + j];
            any += m;
            s += m ? demb[id * PD + tid] : 0.0f;
        }
        if (any == 0) s = demb[tid];
        sg[tid] = s + demb[PD + tid];
    }
    __syncthreads();

    if (tid < MEM) {
        const float* Wd = W0w + (long)(EMBD + 2 * PD) * MEM;   // rows 360..389
        float acc = 2.0f * W0b[tid];
        #pragma unroll
        for (int k = 0; k < PD; k++) acc += sg[k] * Wd[k * MEM + tid];
        g_c[bt * MEM + tid] = acc;
    }
}

// ---------------- K1b: transpose + split + pad the weight matrices ----------------
__global__ void k_wsplit(const float* __restrict__ W0, const float* __restrict__ W1) {
    int idx = blockIdx.x * 256 + threadIdx.x;
    if (idx < NP * KP0) {
        int n = idx / KP0, k = idx % KP0;
        float v = (n < MEM && k < EMBD + 2 * PD) ? W0[(long)k * MEM + n] : 0.0f;
        __nv_bfloat16 h, l; bsplit(v, h, l);
        g_w0h[idx] = h; g_w0l[idx] = l;
    }
    if (idx < NP * KP1) {
        int n = idx / KP1, k = idx % KP1;
        float v = (n < MEM && k < MEM) ? W1[(long)k * MEM + n] : 0.0f;
        __nv_bfloat16 h, l; bsplit(v, h, l);
        g_w1h[idx] = h; g_w1l[idx] = l;
    }
}

// ---------------- dense GEMM: y[b][s][n] = (x @ W^T), cp.async double-buffered ----------------
// CTA 128x64, 4 warps (2m x 2n), warp tile 64x32, BK=32, 3-product split bf16.
// Dynamic smem: 2 buffers x (Ah 128x40 | Al 128x40 | Bh 64x40 | Bl 64x40) bf16.
template <int KPAD>
__global__ __launch_bounds__(128)
void k_dense(const __nv_bfloat16* __restrict__ Ah, const __nv_bfloat16* __restrict__ Al,
             const __nv_bfloat16* __restrict__ Wh, const __nv_bfloat16* __restrict__ Wl,
             __nv_bfloat16* __restrict__ Yh, __nv_bfloat16* __restrict__ Yl) {
    extern __shared__ __nv_bfloat16 dsm[];
    const int OAh = 0, OAl = 5120, OBh = 10240, OBl = 12800, BUFE = 15360; // elem offsets

    int tid = threadIdx.x, lane = tid & 31, wid = tid >> 5;
    int wm = wid >> 1, wn = wid & 1;
    long m0 = (long)blockIdx.y * 128;
    int  n0 = blockIdx.x * 64;

    const int NCH = KPAD / 32;

    auto stage = [&](int ch, int buf) {
        int k0 = ch * 32;
        __nv_bfloat16* base = dsm + buf * BUFE;
        #pragma unroll
        for (int i = 0; i < 4; i++) {
            int idx = tid + i * 128;
            int r = idx >> 2, g = idx & 3;
            cp16(smem_u32(base + OAh + r * 40 + g * 8), Ah + (m0 + r) * KPAD + k0 + g * 8);
            cp16(smem_u32(base + OAl + r * 40 + g * 8), Al + (m0 + r) * KPAD + k0 + g * 8);
        }
        #pragma unroll
        for (int i = 0; i < 2; i++) {
            int idx = tid + i * 128;
            int r = idx >> 2, g = idx & 3;
            cp16(smem_u32(base + OBh + r * 40 + g * 8), Wh + (long)(n0 + r) * KPAD + k0 + g * 8);
            cp16(smem_u32(base + OBl + r * 40 + g * 8), Wl + (long)(n0 + r) * KPAD + k0 + g * 8);
        }
        cp_commit();
    };

    float acc[4][4][4];
    #pragma unroll
    for (int i = 0; i < 4; i++)
        #pragma unroll
        for (int j = 0; j < 4; j++)
            #pragma unroll
            for (int q = 0; q < 4; q++) acc[i][j][q] = 0.0f;

    stage(0, 0);
    for (int ch = 0; ch < NCH; ch++) {
        int buf = ch & 1;
        if (ch + 1 < NCH) { stage(ch + 1, buf ^ 1); cp_wait<1>(); }
        else              { cp_wait<0>(); }
        __syncthreads();

        uint32_t uAh = smem_u32(dsm + buf * BUFE + OAh);
        uint32_t uAl = smem_u32(dsm + buf * BUFE + OAl);
        uint32_t uBh = smem_u32(dsm + buf * BUFE + OBh);
        uint32_t uBl = smem_u32(dsm + buf * BUFE + OBl);

        #pragma unroll
        for (int ks = 0; ks < 32; ks += 16) {
            uint32_t ah[4][4], al[4][4], bh[4][2], bl[4][2];
            #pragma unroll
            for (int mi = 0; mi < 4; mi++) {
                uint32_t off = (uint32_t)(((wm * 64 + mi * 16 + (lane & 15)) * 40 +
                                           ks + ((lane >> 4) << 3)) * 2);
                ldm_x4(ah[mi], uAh + off);
                ldm_x4(al[mi], uAl + off);
            }
            #pragma unroll
            for (int ni = 0; ni < 4; ni++) {
                uint32_t off = (uint32_t)(((wn * 32 + ni * 8 + (lane & 7)) * 40 +
                                           ks + (((lane >> 3) & 1) << 3)) * 2);
                ldm_x2(bh[ni], uBh + off);
                ldm_x2(bl[ni], uBl + off);
            }
            #pragma unroll
            for (int mi = 0; mi < 4; mi++)
                #pragma unroll
                for (int ni = 0; ni < 4; ni++) {
                    mma_bf16(acc[mi][ni], ah[mi], bh[ni]);
                    mma_bf16(acc[mi][ni], ah[mi], bl[ni]);
                    mma_bf16(acc[mi][ni], al[mi], bh[ni]);
                }
        }
        __syncthreads();
    }

    // epilogue: write y split bf16, natural [b][s][n]
    #pragma unroll
    for (int mi = 0; mi < 4; mi++) {
        #pragma unroll
        for (int half = 0; half < 2; half++) {
            long row = m0 + wm * 64 + mi * 16 + (lane >> 2) + half * 8;
            long b = row / TT;
            int  s = (int)(row % TT);
            long base = (b * SP + s) * NP;
            #pragma unroll
            for (int ni = 0; ni < 4; ni++) {
                int n = n0 + wn * 32 + ni * 8 + (lane & 3) * 2;
                float v0 = acc[mi][ni][half * 2 + 0];
                float v1 = acc[mi][ni][half * 2 + 1];
                __nv_bfloat16 h0, l0, h1, l1;
                bsplit(v0, h0, l0); bsplit(v1, h1, l1);
                *(uint32_t*)&Yh[base + n] = bpack(h0, h1);
                *(uint32_t*)&Yl[base + n] = bpack(l0, l1);
            }
        }
    }
}

// ---------------- adjacency GEMM: D = (A+I) @ y, cp.async double-buffered ----------------
__global__ __launch_bounds__(128)
void k_adj(const __nv_bfloat16* __restrict__ Yh, const __nv_bfloat16* __restrict__ Yl,
           const float* __restrict__ cvec, const float* __restrict__ bias,
           __nv_bfloat16* __restrict__ Hh, __nv_bfloat16* __restrict__ Hl,
           float* __restrict__ outp, int layer0) {
    __shared__ __nv_bfloat16 sA[2][128 * 40];
    __shared__ __nv_bfloat16 sYh[2][32 * 72], sYl[2][32 * 72];

    int tid = threadIdx.x, lane = tid & 31, wid = tid >> 5;
    int wm = wid >> 1, wn = wid & 1;
    int b  = blockIdx.z;
    int m0 = blockIdx.y * 72;       // 0 or 72 (tiles overlap; identical values)
    int n0 = blockIdx.x * 64;

    auto stage = [&](int ch, int buf) {
        int k0 = ch * 32;
        #pragma unroll
        for (int i = 0; i < 4; i++) {
            int idx = tid + i * 128;
            int r = idx >> 2, g = idx & 3;
            cp16(smem_u32(&sA[buf][r * 40 + g * 8]),
                 &g_ab[((long)b * TT + m0 + r) * SP + k0 + g * 8]);
        }
        #pragma unroll
        for (int i = 0; i < 2; i++) {
            int idx = tid + i * 128;
            int r = idx >> 3, g = idx & 7;
            long gb = ((long)b * SP + k0 + r) * NP + n0 + g * 8;
            cp16(smem_u32(&sYh[buf][r * 72 + g * 8]), &Yh[gb]);
            cp16(smem_u32(&sYl[buf][r * 72 + g * 8]), &Yl[gb]);
        }
        cp_commit();
    };

    float acc[4][4][4];
    #pragma unroll
    for (int i = 0; i < 4; i++)
        #pragma unroll
        for (int j = 0; j < 4; j++)
            #pragma unroll
            for (int q = 0; q < 4; q++) acc[i][j][q] = 0.0f;

    const int NCH = SP / 32;   // 7
    stage(0, 0);
    for (int ch = 0; ch < NCH; ch++) {
        int buf = ch & 1;
        if (ch + 1 < NCH) { stage(ch + 1, buf ^ 1); cp_wait<1>(); }
        else              { cp_wait<0>(); }
        __syncthreads();

        uint32_t uA  = smem_u32(sA[buf]);
        uint32_t uYh = smem_u32(sYh[buf]);
        uint32_t uYl = smem_u32(sYl[buf]);

        #pragma unroll
        for (int ks = 0; ks < 32; ks += 16) {
            uint32_t aa[4][4], bh[4][2], bl[4][2];
            #pragma unroll
            for (int mi = 0; mi < 4; mi++) {
                uint32_t off = (uint32_t)(((wm * 64 + mi * 16 + (lane & 15)) * 40 +
                                           ks + ((lane >> 4) << 3)) * 2);
                ldm_x4(aa[mi], uA + off);
            }
            #pragma unroll
            for (int ni = 0; ni < 4; ni++) {
                uint32_t off = (uint32_t)(((ks + (lane & 15)) * 72 +
                                           wn * 32 + ni * 8) * 2);
                ldm_x2t(bh[ni], uYh + off);
                ldm_x2t(bl[ni], uYl + off);
            }
            #pragma unroll
            for (int mi = 0; mi < 4; mi++)
                #pragma unroll
                for (int ni = 0; ni < 4; ni++) {
                    mma_bf16(acc[mi][ni], aa[mi], bh[ni]);
                    mma_bf16(acc[mi][ni], aa[mi], bl[ni]);
                }
        }
        __syncthreads();
    }

    // fused epilogue
    #pragma unroll
    for (int mi = 0; mi < 4; mi++) {
        #pragma unroll
        for (int half = 0; half < 2; half++) {
            int t = m0 + wm * 64 + mi * 16 + (lane >> 2) + half * 8;   // < 200
            long bt = (long)b * TT + t;
            float rd = g_rd[bt];
            #pragma unroll
            for (int ni = 0; ni < 4; ni++) {
                int n = n0 + wn * 32 + ni * 8 + (lane & 3) * 2;
                if (n >= MEM) continue;
                float a0, a1;
                if (layer0) { a0 = cvec[bt * MEM + n]; a1 = cvec[bt * MEM + n + 1]; }
                else        { a0 = 2.0f * bias[n];     a1 = 2.0f * bias[n + 1]; }
                float v0 = (acc[mi][ni][half * 2 + 0] + a0) * rd;
                float v1 = (acc[mi][ni][half * 2 + 1] + a1) * rd;
                v0 = v0 > 0.0f ? v0 : 0.0f;
                v1 = v1 > 0.0f ? v1 : 0.0f;
                if (layer0) {
                    __nv_bfloat16 h0, l0, h1, l1;
                    bsplit(v0, h0, l0); bsplit(v1, h1, l1);
                    *(uint32_t*)&Hh[bt * KP1 + n] = bpack(h0, h1);
                    *(uint32_t*)&Hl[bt * KP1 + n] = bpack(l0, l1);
                } else {
                    *(float2*)&outp[bt * MEM + n] = make_float2(v0, v1);
                }
            }
        }
    }
}

// ---------------- launch ----------------
extern "C" void kernel_launch(void* const* d_in, const int* in_sizes, int n_in,
                              void* d_out, int out_size) {
    const int*   adj      = (const int*)d_in[0];
    const int*   words    = (const int*)d_in[1];
    const int*   pos      = (const int*)d_in[2];
    const int*   ner      = (const int*)d_in[3];
    const int*   dep_ids  = (const int*)d_in[4];
    const int*   dep_mask = (const int*)d_in[5];
    const float* wemb = (const float*)d_in[7];
    const float* pemb = (const float*)d_in[8];
    const float* nemb = (const float*)d_in[9];
    const float* demb = (const float*)d_in[10];
    const float* W0w  = (const float*)d_in[11];
    const float* W0b  = (const float*)d_in[12];
    const float* W1w  = (const float*)d_in[13];
    const float* W1b  = (const float*)d_in[14];
    float* out = (float*)d_out;

    const int SMEM_DENSE = 2 * 15360 * 2;   // 61440 bytes
    cudaFuncSetAttribute(k_dense<KP0>, cudaFuncAttributeMaxDynamicSharedMemorySize, SMEM_DENSE);
    cudaFuncSetAttribute(k_dense<KP1>, cudaFuncAttributeMaxDynamicSharedMemorySize, SMEM_DENSE);

    __nv_bfloat16 *xh, *xl, *hh, *hl, *yh, *yl, *zh, *zl, *w0h, *w0l, *w1h, *w1l;
    float* pc;
    cudaGetSymbolAddress((void**)&xh,  g_xh);  cudaGetSymbolAddress((void**)&xl,  g_xl);
    cudaGetSymbolAddress((void**)&hh,  g_hh);  cudaGetSymbolAddress((void**)&hl,  g_hl);
    cudaGetSymbolAddress((void**)&yh,  g_yh);  cudaGetSymbolAddress((void**)&yl,  g_yl);
    cudaGetSymbolAddress((void**)&zh,  g_zh);  cudaGetSymbolAddress((void**)&zl,  g_zl);
    cudaGetSymbolAddress((void**)&w0h, g_w0h); cudaGetSymbolAddress((void**)&w0l, g_w0l);
    cudaGetSymbolAddress((void**)&w1h, g_w1h); cudaGetSymbolAddress((void**)&w1l, g_w1l);
    cudaGetSymbolAddress((void**)&pc,  g_c);

    int write_mask = (out_size >= (int)(BT * MEM + BT));

    k_prep<<<BATCH, 256>>>(adj, out, write_mask);
    k_adjconv<<<(int)((long)BATCH * TT * (TT / 4) / 256), 256>>>(adj);
    k_embed<<<(int)BT, 384>>>(words, pos, ner, dep_ids, dep_mask,
                              wemb, pemb, nemb, demb, W0w, W0b);
    k_wsplit<<<(NP * KP0 + 255) / 256, 256>>>(W0w, W1w);

    dim3 gd(NP / 64, (int)(BT / 128));         // (5, 400)
    dim3 ga(NP / 64, 2, BATCH);                // (5, 2, 256)

    // layer 0
    k_dense<KP0><<<gd, 128, SMEM_DENSE>>>(xh, xl, w0h, w0l, yh, yl);
    k_adj<<<ga, 128>>>(yh, yl, pc, nullptr, hh, hl, nullptr, 1);

    // layer 1
    k_dense<KP1><<<gd, 128, SMEM_DENSE>>>(hh, hl, w1h, w1l, zh, zl);
    k_adj<<<ga, 128>>>(zh, zl, nullptr, W1b, nullptr, nullptr, out, 0);
}